// round 9
// baseline (speedup 1.0000x reference)
#include <cuda_runtime.h>

// Problem constants
#define Bc 4
#define Lc 2048
#define Dc 8192
#define Kc 4
#define QKc 2048
#define Vc 4096

#define CHUNK 64
#define THREADS 256
#define D4 (Dc / 4)            // 2048 float4 lanes across D

// output layout: [ q (B,L,QK) | k (B,L,QK) | v (B,L,V) | new_cache (B,D,K) ]
// all offsets fit comfortably in int32 (total out = 67,141,632 floats)
#define Q_F4   (Bc * Lc * (QKc / 4))            // 4,194,304 float4
#define V_F4   (Bc * Lc * (Vc / 4))             // 8,388,608 float4
#define NC_OFF4 (2 * Q_F4 + V_F4)               // float4 offset of new_cache

__device__ __forceinline__ float silu(float v) {
    // fast sigmoid: MUFU.EX2 + MUFU.RCP path (~2 ulp, tolerance is 1e-3)
    const float e = __expf(-v);
    return v * __fdividef(1.0f, 1.0f + e);
}

__global__ __launch_bounds__(THREADS, 5)     // cap at 51 regs -> 5 blocks/SM, 40 warps
void conv_silu_kernel(const float* __restrict__ x,
                      const float* __restrict__ cache,
                      const float* __restrict__ weight,
                      float* __restrict__ out)
{
    const int d4 = blockIdx.x * THREADS + threadIdx.x;   // float4 lane in D: 0..2047
    const int d  = d4 * 4;                               // first scalar channel
    const int b  = blockIdx.z;
    const int l0 = blockIdx.y * CHUNK;
    const bool last = (l0 + CHUNK == Lc);

    const float4* x4 = (const float4*)x;
    const float4* w4 = (const float4*)weight;            // weight (D,K=4): row d = one float4

    // per-channel weights for d..d+3
    const float4 w0 = w4[d + 0];
    const float4 w1 = w4[d + 1];
    const float4 w2 = w4[d + 2];
    const float4 w3 = w4[d + 3];

    // sliding window: r0..r2 = xf rows l0..l0+2 (i.e., x rows l0-3..l0-1)
    float4 r0, r1, r2;
    if (l0 == 0) {
        // xf[0..2] come from cache[:, :, 1..3]; cache (B,D,K=4) -> float4 per channel
        const float4* c4 = (const float4*)cache + b * Dc + d;
        const float4 c0 = c4[0], c1 = c4[1], c2 = c4[2], c3 = c4[3];
        r0 = make_float4(c0.y, c1.y, c2.y, c3.y);
        r1 = make_float4(c0.z, c1.z, c2.z, c3.z);
        r2 = make_float4(c0.w, c1.w, c2.w, c3.w);
    } else {
        const float4* xb = x4 + (b * Lc + (l0 - 3)) * D4 + d4;   // int arithmetic, fits
        r0 = __ldcs(&xb[0]);
        r1 = __ldcs(&xb[D4]);
        r2 = __ldcs(&xb[2 * D4]);
    }

    // output base: segment boundaries (2048, 4096) are float4-aligned, so the whole
    // float4 lane lives in one segment. 32-bit offsets throughout.
    int obase, stride4;
    if (d < QKc) {                                // q
        stride4 = QKc / 4;
        obase   = (b * Lc + l0) * stride4 + d4;
    } else if (d < 2 * QKc) {                     // k
        stride4 = QKc / 4;
        obase   = Q_F4 + (b * Lc + l0) * stride4 + (d4 - QKc / 4);
    } else {                                      // v
        stride4 = Vc / 4;
        obase   = 2 * Q_F4 + (b * Lc + l0) * stride4 + (d4 - 2 * (QKc / 4));
    }
    float4*       o4  = (float4*)out + obase;
    const float4* xin = x4 + (b * Lc + l0) * D4 + d4;    // xf[l+3] == x[b, l, :]

#pragma unroll 8
    for (int i = 0; i < CHUNK; ++i) {
        const float4 r3 = __ldcs(&xin[i * D4]);
        float4 y;
        y.x = silu(w0.x * r0.x + w0.y * r1.x + w0.z * r2.x + w0.w * r3.x);
        y.y = silu(w1.x * r0.y + w1.y * r1.y + w1.z * r2.y + w1.w * r3.y);
        y.z = silu(w2.x * r0.z + w2.y * r1.z + w2.z * r2.z + w2.w * r3.z);
        y.w = silu(w3.x * r0.w + w3.y * r1.w + w3.z * r2.w + w3.w * r3.w);
        __stcs(&o4[i * stride4], y);

        // fused conv-state update: at the final iteration of the last chunk the
        // window registers hold exactly x rows L-4..L-1 for channels d..d+3.
        // new_cache (B,D,K): 4x4 register transpose, 4 coalesced float4 stores.
        if (last && i == CHUNK - 1) {
            float4* nc = (float4*)out + NC_OFF4 + b * Dc + d;
            nc[0] = make_float4(r0.x, r1.x, r2.x, r3.x);
            nc[1] = make_float4(r0.y, r1.y, r2.y, r3.y);
            nc[2] = make_float4(r0.z, r1.z, r2.z, r3.z);
            nc[3] = make_float4(r0.w, r1.w, r2.w, r3.w);
        }

        r0 = r1; r1 = r2; r2 = r3;
    }
}

extern "C" void kernel_launch(void* const* d_in, const int* in_sizes, int n_in,
                              void* d_out, int out_size)
{
    const float* x      = (const float*)d_in[0];
    const float* cache  = (const float*)d_in[1];
    const float* weight = (const float*)d_in[2];
    float*       out    = (float*)d_out;

    dim3 grid(D4 / THREADS, Lc / CHUNK, Bc);   // (8, 32, 4) = 1024 blocks
    conv_silu_kernel<<<grid, THREADS>>>(x, cache, weight, out);
}

// round 10
// speedup vs baseline: 1.3489x; 1.3489x over previous
#include <cuda_runtime.h>

// Problem constants
#define Bc 4
#define Lc 2048
#define Dc 8192
#define Kc 4
#define QKc 2048
#define Vc 4096

#define CHUNK 64
#define THREADS 256
#define UNROLL 8
#define D4 (Dc / 4)            // 2048 float4 lanes across D

// output layout: [ q (B,L,QK) | k (B,L,QK) | v (B,L,V) | new_cache (B,D,K) ]
// all offsets fit comfortably in int32 (total out = 67,141,632 floats)
#define Q_F4   (Bc * Lc * (QKc / 4))            // 4,194,304 float4
#define V_F4   (Bc * Lc * (Vc / 4))             // 8,388,608 float4
#define NC_OFF4 (2 * Q_F4 + V_F4)               // float4 offset of new_cache

__device__ __forceinline__ float silu(float v) {
    // fast sigmoid: MUFU.EX2 + MUFU.RCP path (~2 ulp, tolerance is 1e-3)
    const float e = __expf(-v);
    return v * __fdividef(1.0f, 1.0f + e);
}

__global__ __launch_bounds__(THREADS)        // no min-blocks cap: R9 showed it hurts MLP
void conv_silu_kernel(const float* __restrict__ x,
                      const float* __restrict__ cache,
                      const float* __restrict__ weight,
                      float* __restrict__ out)
{
    const int d4 = blockIdx.x * THREADS + threadIdx.x;   // float4 lane in D: 0..2047
    const int d  = d4 * 4;                               // first scalar channel
    const int b  = blockIdx.z;
    const int l0 = blockIdx.y * CHUNK;
    const bool last = (l0 + CHUNK == Lc);

    const float4* x4 = (const float4*)x;
    const float4* w4 = (const float4*)weight;            // weight (D,K=4): row d = one float4

    // per-channel weights for d..d+3
    const float4 w0 = w4[d + 0];
    const float4 w1 = w4[d + 1];
    const float4 w2 = w4[d + 2];
    const float4 w3 = w4[d + 3];

    // sliding window: r0..r2 = xf rows l0..l0+2 (i.e., x rows l0-3..l0-1)
    float4 r0, r1, r2;
    if (l0 == 0) {
        // xf[0..2] come from cache[:, :, 1..3]; cache (B,D,K=4) -> float4 per channel
        const float4* c4 = (const float4*)cache + b * Dc + d;
        const float4 c0 = c4[0], c1 = c4[1], c2 = c4[2], c3 = c4[3];
        r0 = make_float4(c0.y, c1.y, c2.y, c3.y);
        r1 = make_float4(c0.z, c1.z, c2.z, c3.z);
        r2 = make_float4(c0.w, c1.w, c2.w, c3.w);
    } else {
        const float4* xb = x4 + (b * Lc + (l0 - 3)) * D4 + d4;
        r0 = __ldcs(&xb[0]);
        r1 = __ldcs(&xb[D4]);
        r2 = __ldcs(&xb[2 * D4]);
    }

    // output base: segment boundaries (2048, 4096) are float4-aligned, so the whole
    // float4 lane lives in one segment. 32-bit offsets throughout.
    int obase, stride4;
    if (d < QKc) {                                // q
        stride4 = QKc / 4;
        obase   = (b * Lc + l0) * stride4 + d4;
    } else if (d < 2 * QKc) {                     // k
        stride4 = QKc / 4;
        obase   = Q_F4 + (b * Lc + l0) * stride4 + (d4 - QKc / 4);
    } else {                                      // v
        stride4 = Vc / 4;
        obase   = 2 * Q_F4 + (b * Lc + l0) * stride4 + (d4 - 2 * (QKc / 4));
    }
    float4*       o4  = (float4*)out + obase;
    const float4* xin = x4 + (b * Lc + l0) * D4 + d4;    // xf[l+3] == x[b, l, :]

#pragma unroll 1
    for (int ii = 0; ii < CHUNK; ii += UNROLL) {
        // ---- phase 1: batch-issue all UNROLL independent loads (forces MLP_p1 = 8) ----
        float4 t[UNROLL];
#pragma unroll
        for (int u = 0; u < UNROLL; ++u)
            t[u] = __ldcs(&xin[(ii + u) * D4]);

        // ---- phase 2: compute + store while loads for the NEXT group can overlap ----
#pragma unroll
        for (int u = 0; u < UNROLL; ++u) {
            const float4 r3 = t[u];
            float4 y;
            y.x = silu(w0.x * r0.x + w0.y * r1.x + w0.z * r2.x + w0.w * r3.x);
            y.y = silu(w1.x * r0.y + w1.y * r1.y + w1.z * r2.y + w1.w * r3.y);
            y.z = silu(w2.x * r0.z + w2.y * r1.z + w2.z * r2.z + w2.w * r3.z);
            y.w = silu(w3.x * r0.w + w3.y * r1.w + w3.z * r2.w + w3.w * r3.w);
            __stcs(&o4[(ii + u) * stride4], y);

            // fused conv-state update: in the final iteration of the last chunk the
            // window registers hold exactly x rows L-4..L-1 for channels d..d+3.
            // new_cache (B,D,K): 4x4 register transpose, 4 coalesced float4 stores.
            if (last && (ii + u == CHUNK - 1)) {
                float4* nc = (float4*)out + NC_OFF4 + b * Dc + d;
                nc[0] = make_float4(r0.x, r1.x, r2.x, r3.x);
                nc[1] = make_float4(r0.y, r1.y, r2.y, r3.y);
                nc[2] = make_float4(r0.z, r1.z, r2.z, r3.z);
                nc[3] = make_float4(r0.w, r1.w, r2.w, r3.w);
            }

            r0 = r1; r1 = r2; r2 = r3;
        }
    }
}

extern "C" void kernel_launch(void* const* d_in, const int* in_sizes, int n_in,
                              void* d_out, int out_size)
{
    const float* x      = (const float*)d_in[0];
    const float* cache  = (const float*)d_in[1];
    const float* weight = (const float*)d_in[2];
    float*       out    = (float*)d_out;

    dim3 grid(D4 / THREADS, Lc / CHUNK, Bc);   // (8, 32, 4) = 1024 blocks
    conv_silu_kernel<<<grid, THREADS>>>(x, cache, weight, out);
}